// round 7
// baseline (speedup 1.0000x reference)
#include <cuda_runtime.h>
#include <cuda_bf16.h>
#include <cstdint>

// ============================================================================
// BinaryToCost: out[i] = x_i @ Q @ x_i  (x: 1024x2048 {0,1} fp32, Q: 2048^2 fp32)
// Split-precision bf16 mma.sync GEMM (Q = Qhi + Qlo), z-split over 2 passes,
// A-operand synthesized from a BITMASK of x (no A smem tiles / no A ldmatrix),
// B via cp.async+ldmatrix, fused masked row-reduce, last-CTA final reduction.
// ============================================================================

#define NDIM 2048
#define BDIM 1024
#define BM 128
#define BN 128
#define BK 64              // K elems per chunk
#define NCHUNK 32          // chunks per CTA (one full-K pass)
#define NT (NDIM / BN)     // 16
#define MT (BDIM / BM)     // 8
#define NCTA (NT * MT * 2) // 256
#define NSTAGE 4
#define STAGE_BYTES 17408  // B tile 16KB + bitmask 1KB (both 1KB-aligned)
#define SMEM_BYTES (NSTAGE * STAGE_BYTES)

// ---------------------------------------------------------------------------
__device__ __align__(16) __nv_bfloat16 g_qhi[NDIM * NDIM];  // bf16(Q) row-major
__device__ __align__(16) __nv_bfloat16 g_qlo[NDIM * NDIM];  // bf16 resid
__device__ __align__(16) unsigned long long g_xb[32 * BDIM]; // [k/64][m] bitmask
__device__ float g_partial[2 * NT * BDIM];
__device__ unsigned g_cnt = 0;

// ---------------------------------------------------------------------------
__device__ __forceinline__ uint32_t smem_u32(const void* p) {
    return (uint32_t)__cvta_generic_to_shared(p);
}
__device__ __forceinline__ uint32_t sw128(uint32_t off) {
    return off ^ ((off >> 3) & 0x70);
}
__device__ __forceinline__ void cp_async16(uint32_t dst, const void* src) {
    asm volatile("cp.async.cg.shared.global [%0], [%1], 16;"
                 :: "r"(dst), "l"(src) : "memory");
}

#define LDSM_X4(r, addr)                                                      \
    asm volatile("ldmatrix.sync.aligned.m8n8.x4.shared.b16 {%0,%1,%2,%3}, [%4];" \
                 : "=r"((r)[0]), "=r"((r)[1]), "=r"((r)[2]), "=r"((r)[3])     \
                 : "r"(addr))

__device__ __forceinline__ void mma16816(float* d, const uint32_t* a,
                                         const uint32_t* b) {
    asm volatile(
        "mma.sync.aligned.m16n8k16.row.col.f32.bf16.bf16.f32 "
        "{%0,%1,%2,%3}, {%4,%5,%6,%7}, {%8,%9}, {%0,%1,%2,%3};"
        : "+f"(d[0]), "+f"(d[1]), "+f"(d[2]), "+f"(d[3])
        : "r"(a[0]), "r"(a[1]), "r"(a[2]), "r"(a[3]), "r"(b[0]), "r"(b[1]));
}

// 2 bits -> bf16x2 of {0,1}: lo = b&1 ? 1.0bf : 0, hi = b&2 ? 1.0bf : 0
__device__ __forceinline__ uint32_t expand2(uint32_t b) {
    return (b & 1u) * 0x00003F80u + (b & 2u) * 0x1FC00000u;
}

// ---------------------------------------------------------------------------
// Prep: blocks [0,2048) stream-split Q into (qhi, qlo); blocks [2048,2304)
// bitpack x via warp ballots into g_xb[k/64][m].
// ---------------------------------------------------------------------------
__global__ void __launch_bounds__(256)
k_prep(const float* __restrict__ x, const float* __restrict__ Q) {
    const int b = blockIdx.x;
    if (b < 2048) {
        int i = b * 256 + threadIdx.x;  // 8-elem group index over Q
        const float4* q4 = reinterpret_cast<const float4*>(Q) + i * 2;
        float4 v0 = q4[0], v1 = q4[1];
        float vv[8] = {v0.x, v0.y, v0.z, v0.w, v1.x, v1.y, v1.z, v1.w};
        __nv_bfloat16 h[8], l[8];
#pragma unroll
        for (int e = 0; e < 8; ++e) {
            h[e] = __float2bfloat16(vv[e]);
            l[e] = __float2bfloat16(vv[e] - __bfloat162float(h[e]));
        }
        reinterpret_cast<uint4*>(g_qhi)[i] = *reinterpret_cast<uint4*>(h);
        reinterpret_cast<uint4*>(g_qlo)[i] = *reinterpret_cast<uint4*>(l);
    } else {
        int b2 = b - 2048;
        int wid = threadIdx.x >> 5;
        int lane = threadIdx.x & 31;
        int wbase = (b2 * 8 + wid) * 16;
#pragma unroll
        for (int j = 0; j < 16; ++j) {
            int widx = wbase + j;            // widx = c*1024 + m
            int c = widx >> 10, m = widx & 1023;
            float v0 = x[m * NDIM + c * 64 + lane];
            float v1 = x[m * NDIM + c * 64 + 32 + lane];
            unsigned lo = __ballot_sync(0xFFFFFFFFu, v0 != 0.0f);
            unsigned hi = __ballot_sync(0xFFFFFFFFu, v1 != 0.0f);
            if (lane == 0)
                g_xb[widx] = (unsigned long long)lo |
                             ((unsigned long long)hi << 32);
        }
    }
}

// ---------------------------------------------------------------------------
// GEMM: grid (NT, MT, 2), 256 threads (8 warps: 2M x 4N, warp tile 64x32),
// 2 CTAs/SM. A from bitmask, B from smem via ldmatrix.
// ---------------------------------------------------------------------------
__global__ void __launch_bounds__(256, 2)
k_gemm(const float* __restrict__ x, float* __restrict__ out) {
    extern __shared__ __align__(1024) uint8_t smem[];

    const int tid = threadIdx.x;
    const int wid = tid >> 5;
    const int lane = tid & 31;
    const int n0 = blockIdx.x * BN;
    const int m0 = blockIdx.y * BM;
    const int wm = (wid >> 2) * 64;
    const int wn = (wid & 3) * 32;
    const int grp = lane >> 3;     // ldmatrix quadrant (B)
    const int ri = lane & 7;
    const int g4 = lane >> 2;      // mma group id
    const int tc2 = (lane & 3) * 2;
    const __nv_bfloat16* __restrict__ qs = blockIdx.z ? g_qlo : g_qhi;

    auto stage_load = [&](int c) {
        uint32_t sb = smem_u32(smem) + (c % NSTAGE) * STAGE_BYTES;
        int kbE = c * BK;
#pragma unroll
        for (int i = 0; i < 4; ++i) {
            int g = tid + 256 * i;
            int rr = g >> 3;
            int cc = g & 7;
            uint32_t off = sw128((uint32_t)(rr * 128 + cc * 16));
            cp_async16(sb + off, qs + (n0 + rr) * NDIM + kbE + cc * 8);
        }
        if (tid < 64)  // 1KB bitmask slab: g_xb[c][m0 .. m0+127]
            cp_async16(sb + 16384 + tid * 16,
                       reinterpret_cast<const uint8_t*>(g_xb) + c * 8192 +
                           m0 * 8 + tid * 16);
        asm volatile("cp.async.commit_group;" ::: "memory");
    };

    float cfrag[4][4][4];
#pragma unroll
    for (int mt = 0; mt < 4; ++mt)
#pragma unroll
        for (int nt = 0; nt < 4; ++nt)
#pragma unroll
            for (int r = 0; r < 4; ++r) cfrag[mt][nt][r] = 0.0f;

    stage_load(0);
    stage_load(1);
    stage_load(2);

    for (int ch = 0; ch < NCHUNK; ++ch) {
        if (ch < NCHUNK - 2)
            asm volatile("cp.async.wait_group 2;" ::: "memory");
        else if (ch == NCHUNK - 2)
            asm volatile("cp.async.wait_group 1;" ::: "memory");
        else
            asm volatile("cp.async.wait_group 0;" ::: "memory");
        __syncthreads();

        if (ch + 3 < NCHUNK) stage_load(ch + 3);

        const int so = (ch % NSTAGE) * STAGE_BYTES;
        const uint32_t sb = smem_u32(smem) + so;
        const unsigned long long* bmp =
            reinterpret_cast<const unsigned long long*>(smem + so + 16384);

        // per-chunk bitmask words for this thread's 8 A rows
        unsigned long long w0[4], w1[4];
#pragma unroll
        for (int mt = 0; mt < 4; ++mt) {
            int r = wm + mt * 16 + g4;
            w0[mt] = bmp[r];
            w1[mt] = bmp[r + 8];
        }

#pragma unroll
        for (int s = 0; s < 4; ++s) {  // 4 k16-steps per chunk
            const int kb = s * 32;
            uint32_t b[2][4];
#pragma unroll
            for (int nt2 = 0; nt2 < 2; ++nt2) {
                int row = wn + nt2 * 16 + (grp >> 1) * 8 + ri;
                uint32_t addr = sb + sw128((uint32_t)(row * 128 + kb + (grp & 1) * 16));
                LDSM_X4(b[nt2], addr);
            }
#pragma unroll
            for (int mt = 0; mt < 4; ++mt) {
                uint32_t s0 = (uint32_t)(w0[mt] >> (16 * s + tc2));
                uint32_t s1 = (uint32_t)(w1[mt] >> (16 * s + tc2));
                uint32_t a[4];
                a[0] = expand2(s0 & 3u);
                a[1] = expand2(s1 & 3u);
                a[2] = expand2((s0 >> 8) & 3u);
                a[3] = expand2((s1 >> 8) & 3u);
#pragma unroll
                for (int nt = 0; nt < 4; ++nt)
                    mma16816(cfrag[mt][nt], a, &b[nt >> 1][(nt & 1) * 2]);
            }
        }
    }

    // ---- Epilogue: masked row sums (deterministic) ----
    float acc0[4], acc1[4];
#pragma unroll
    for (int mt = 0; mt < 4; ++mt) {
        float a0 = 0.0f, a1 = 0.0f;
        const int r0 = m0 + wm + mt * 16 + g4;
#pragma unroll
        for (int nt = 0; nt < 4; ++nt) {
            const int ng = n0 + wn + nt * 8 + tc2;
            const float* x0 = x + r0 * NDIM + ng;
            const float* x1 = x0 + 8 * NDIM;
            a0 += cfrag[mt][nt][0] * x0[0] + cfrag[mt][nt][1] * x0[1];
            a1 += cfrag[mt][nt][2] * x1[0] + cfrag[mt][nt][3] * x1[1];
        }
        a0 += __shfl_xor_sync(0xFFFFFFFF, a0, 1);
        a0 += __shfl_xor_sync(0xFFFFFFFF, a0, 2);
        a1 += __shfl_xor_sync(0xFFFFFFFF, a1, 1);
        a1 += __shfl_xor_sync(0xFFFFFFFF, a1, 2);
        acc0[mt] = a0;
        acc1[mt] = a1;
    }

    __syncthreads();  // stage smem free; reuse for cross-warp reduction
    float* red = reinterpret_cast<float*>(smem);  // [4 n-groups][128 rows]
    if ((lane & 3) == 0) {
        const int ng = wid & 3;
#pragma unroll
        for (int mt = 0; mt < 4; ++mt) {
            int row = wm + mt * 16 + g4;
            red[ng * 128 + row] = acc0[mt];
            red[ng * 128 + row + 8] = acc1[mt];
        }
    }
    __syncthreads();
    if (tid < 128) {
        float p = red[tid] + red[128 + tid] + red[256 + tid] + red[384 + tid];
        g_partial[(blockIdx.z * NT + blockIdx.x) * BDIM + m0 + tid] = p;
    }

    // ---- Last-CTA final reduction ----
    __shared__ unsigned s_old;
    __syncthreads();
    if (tid == 0) {
        __threadfence();
        s_old = atomicAdd(&g_cnt, 1u);
    }
    __syncthreads();
    if (s_old == NCTA - 1) {
        __threadfence();
        for (int m = tid; m < BDIM; m += 256) {
            float s = 0.0f;
#pragma unroll
            for (int p = 0; p < 2 * NT; ++p) s += g_partial[p * BDIM + m];
            out[m] = s;
        }
        if (tid == 0) g_cnt = 0;  // reset for next graph replay
    }
}

// ---------------------------------------------------------------------------
extern "C" void kernel_launch(void* const* d_in, const int* in_sizes, int n_in,
                              void* d_out, int out_size) {
    const float* x = (const float*)d_in[0];  // [1024, 2048]
    const float* Q = (const float*)d_in[1];  // [2048, 2048]
    float* out = (float*)d_out;              // [1024]

    static bool attr_set = false;
    if (!attr_set) {
        cudaFuncSetAttribute(k_gemm, cudaFuncAttributeMaxDynamicSharedMemorySize,
                             SMEM_BYTES);
        attr_set = true;
    }

    k_prep<<<2048 + 256, 256>>>(x, Q);
    k_gemm<<<dim3(NT, MT, 2), 256, SMEM_BYTES>>>(x, out);
}

// round 8
// speedup vs baseline: 1.3945x; 1.3945x over previous
#include <cuda_runtime.h>
#include <cuda_bf16.h>
#include <cstdint>

// ============================================================================
// BinaryToCost: out[i] = x_i @ Q @ x_i  (x: 1024x2048 {0,1} fp32, Q: 2048^2 fp32)
// Split-precision bf16 mma.sync GEMM (Q = Qhi + Qlo), z-split over 2 passes,
// CTA tile 128x256, warp tile 64x64 (halved smem traffic per MAC), 4-stage
// cp.async pipeline, fused masked row-reduce, last-CTA final reduction.
// Symmetry trick: B reads row-major Q directly (x Q^T x == x Q x elementwise).
// ============================================================================

#define NDIM 2048
#define BDIM 1024
#define BM 128
#define BN 256
#define BK 64               // K elems per chunk (128B rows, SW128 atom)
#define NCHUNK 32           // chunks per CTA (one full-K pass)
#define NTN (NDIM / BN)     // 8
#define MT (BDIM / BM)      // 8
#define NCTA (NTN * MT * 2) // 128
#define NSTAGE 4
#define A_BYTES 16384       // 128 x 64 bf16
#define B_BYTES 32768       // 256 x 64 bf16
#define STAGE_BYTES (A_BYTES + B_BYTES)
#define SMEM_BYTES (NSTAGE * STAGE_BYTES)  // 192 KB

// ---------------------------------------------------------------------------
__device__ __align__(16) __nv_bfloat16 g_xh[BDIM * NDIM];   // bf16(x)  [m][k]
__device__ __align__(16) __nv_bfloat16 g_qhi[NDIM * NDIM];  // bf16(Q)  row-major
__device__ __align__(16) __nv_bfloat16 g_qlo[NDIM * NDIM];  // bf16 resid
__device__ float g_partial[2 * NTN * BDIM];
__device__ unsigned g_cnt = 0;

// ---------------------------------------------------------------------------
__device__ __forceinline__ uint32_t smem_u32(const void* p) {
    return (uint32_t)__cvta_generic_to_shared(p);
}
__device__ __forceinline__ uint32_t sw128(uint32_t off) {
    return off ^ ((off >> 3) & 0x70);
}
__device__ __forceinline__ void cp_async16(uint32_t dst, const void* src) {
    asm volatile("cp.async.cg.shared.global [%0], [%1], 16;"
                 :: "r"(dst), "l"(src) : "memory");
}

#define LDSM_X4(r, addr)                                                      \
    asm volatile("ldmatrix.sync.aligned.m8n8.x4.shared.b16 {%0,%1,%2,%3}, [%4];" \
                 : "=r"((r)[0]), "=r"((r)[1]), "=r"((r)[2]), "=r"((r)[3])     \
                 : "r"(addr))

__device__ __forceinline__ void mma16816(float* d, const uint32_t* a,
                                         const uint32_t* b) {
    asm volatile(
        "mma.sync.aligned.m16n8k16.row.col.f32.bf16.bf16.f32 "
        "{%0,%1,%2,%3}, {%4,%5,%6,%7}, {%8,%9}, {%0,%1,%2,%3};"
        : "+f"(d[0]), "+f"(d[1]), "+f"(d[2]), "+f"(d[3])
        : "r"(a[0]), "r"(a[1]), "r"(a[2]), "r"(a[3]), "r"(b[0]), "r"(b[1]));
}

// ---------------------------------------------------------------------------
// Prep: blocks [0,2048) stream-split Q into (qhi, qlo); rest pack x to bf16.
// ---------------------------------------------------------------------------
__global__ void __launch_bounds__(256)
k_prep(const float* __restrict__ x, const float* __restrict__ Q) {
    const int b = blockIdx.x;
    if (b < 2048) {
        int i = b * 256 + threadIdx.x;  // 8-elem group index over Q
        const float4* q4 = reinterpret_cast<const float4*>(Q) + i * 2;
        float4 v0 = q4[0], v1 = q4[1];
        float vv[8] = {v0.x, v0.y, v0.z, v0.w, v1.x, v1.y, v1.z, v1.w};
        __nv_bfloat16 h[8], l[8];
#pragma unroll
        for (int e = 0; e < 8; ++e) {
            h[e] = __float2bfloat16(vv[e]);
            l[e] = __float2bfloat16(vv[e] - __bfloat162float(h[e]));
        }
        reinterpret_cast<uint4*>(g_qhi)[i] = *reinterpret_cast<uint4*>(h);
        reinterpret_cast<uint4*>(g_qlo)[i] = *reinterpret_cast<uint4*>(l);
    } else {
        int i = (b - 2048) * 256 + threadIdx.x;  // 8-elem group over x
        const float4* x4 = reinterpret_cast<const float4*>(x) + i * 2;
        float4 v0 = x4[0], v1 = x4[1];
        __nv_bfloat162 p[4];
        p[0] = __floats2bfloat162_rn(v0.x, v0.y);
        p[1] = __floats2bfloat162_rn(v0.z, v0.w);
        p[2] = __floats2bfloat162_rn(v1.x, v1.y);
        p[3] = __floats2bfloat162_rn(v1.z, v1.w);
        reinterpret_cast<uint4*>(g_xh)[i] = *reinterpret_cast<uint4*>(p);
    }
}

// ---------------------------------------------------------------------------
// GEMM: grid (NTN, MT, 2), 256 threads. 8 warps as 2(M) x 4(N), warp 64x64.
// z selects Qhi / Qlo pass. 1 CTA/SM.
// ---------------------------------------------------------------------------
__global__ void __launch_bounds__(256, 1)
k_gemm(const float* __restrict__ x, float* __restrict__ out) {
    extern __shared__ __align__(1024) uint8_t smem[];

    const int tid = threadIdx.x;
    const int wid = tid >> 5;
    const int lane = tid & 31;
    const int n0 = blockIdx.x * BN;
    const int m0 = blockIdx.y * BM;
    const int wm = (wid >> 2) * 64;   // warp m-offset
    const int wn = (wid & 3) * 64;    // warp n-offset
    const int grp = lane >> 3;        // ldmatrix quadrant
    const int ri = lane & 7;
    const int g4 = lane >> 2;
    const int tc2 = (lane & 3) * 2;
    const __nv_bfloat16* __restrict__ qs = blockIdx.z ? g_qlo : g_qhi;

    auto stage_load = [&](int c) {
        uint32_t sa = smem_u32(smem) + (c % NSTAGE) * STAGE_BYTES;
        uint32_t sb = sa + A_BYTES;
        int kbE = c * BK;
#pragma unroll
        for (int i = 0; i < 4; ++i) {  // A: 128 rows
            int g = tid + 256 * i;
            int rr = g >> 3;
            int cc = g & 7;
            uint32_t off = sw128((uint32_t)(rr * 128 + cc * 16));
            cp_async16(sa + off, g_xh + (m0 + rr) * NDIM + kbE + cc * 8);
        }
#pragma unroll
        for (int i = 0; i < 8; ++i) {  // B: 256 rows
            int g = tid + 256 * i;
            int rr = g >> 3;
            int cc = g & 7;
            uint32_t off = sw128((uint32_t)(rr * 128 + cc * 16));
            cp_async16(sb + off, qs + (n0 + rr) * NDIM + kbE + cc * 8);
        }
        asm volatile("cp.async.commit_group;" ::: "memory");
    };

    float cfrag[4][8][4];
#pragma unroll
    for (int mt = 0; mt < 4; ++mt)
#pragma unroll
        for (int nt = 0; nt < 8; ++nt)
#pragma unroll
            for (int r = 0; r < 4; ++r) cfrag[mt][nt][r] = 0.0f;

    stage_load(0);
    stage_load(1);
    stage_load(2);

    for (int ch = 0; ch < NCHUNK; ++ch) {
        if (ch < NCHUNK - 2)
            asm volatile("cp.async.wait_group 2;" ::: "memory");
        else if (ch == NCHUNK - 2)
            asm volatile("cp.async.wait_group 1;" ::: "memory");
        else
            asm volatile("cp.async.wait_group 0;" ::: "memory");
        __syncthreads();

        // stage (ch+3)%4 was consumed in iter ch-1 -> safe to overwrite
        if (ch + 3 < NCHUNK) stage_load(ch + 3);

        const uint32_t sa = smem_u32(smem) + (ch % NSTAGE) * STAGE_BYTES;
        const uint32_t sb = sa + A_BYTES;

#pragma unroll
        for (int s = 0; s < 4; ++s) {  // 4 k16-steps per chunk
            const int kb = s * 32;
            uint32_t a[4][4];
#pragma unroll
            for (int mt = 0; mt < 4; ++mt) {
                int row = wm + mt * 16 + (grp & 1) * 8 + ri;
                uint32_t addr = sa + sw128((uint32_t)(row * 128 + kb + (grp >> 1) * 16));
                LDSM_X4(a[mt], addr);
            }
            uint32_t b[4][4];
#pragma unroll
            for (int nt2 = 0; nt2 < 4; ++nt2) {
                int row = wn + nt2 * 16 + (grp >> 1) * 8 + ri;
                uint32_t addr = sb + sw128((uint32_t)(row * 128 + kb + (grp & 1) * 16));
                LDSM_X4(b[nt2], addr);
            }
#pragma unroll
            for (int mt = 0; mt < 4; ++mt)
#pragma unroll
                for (int nt = 0; nt < 8; ++nt)
                    mma16816(cfrag[mt][nt], a[mt], &b[nt >> 1][(nt & 1) * 2]);
        }
    }

    // ---- Epilogue: masked row sums (deterministic) ----
    float acc0[4], acc1[4];
#pragma unroll
    for (int mt = 0; mt < 4; ++mt) {
        float a0 = 0.0f, a1 = 0.0f;
        const int r0 = m0 + wm + mt * 16 + g4;
#pragma unroll
        for (int nt = 0; nt < 8; ++nt) {
            const int ng = n0 + wn + nt * 8 + tc2;
            const float* x0 = x + r0 * NDIM + ng;
            const float* x1 = x0 + 8 * NDIM;
            a0 += cfrag[mt][nt][0] * x0[0] + cfrag[mt][nt][1] * x0[1];
            a1 += cfrag[mt][nt][2] * x1[0] + cfrag[mt][nt][3] * x1[1];
        }
        a0 += __shfl_xor_sync(0xFFFFFFFF, a0, 1);
        a0 += __shfl_xor_sync(0xFFFFFFFF, a0, 2);
        a1 += __shfl_xor_sync(0xFFFFFFFF, a1, 1);
        a1 += __shfl_xor_sync(0xFFFFFFFF, a1, 2);
        acc0[mt] = a0;
        acc1[mt] = a1;
    }

    __syncthreads();  // stage smem free; reuse for cross-warp reduction
    float* red = reinterpret_cast<float*>(smem);  // [4 n-groups][128 rows]
    if ((lane & 3) == 0) {
        const int ng = wid & 3;
#pragma unroll
        for (int mt = 0; mt < 4; ++mt) {
            int row = wm + mt * 16 + g4;
            red[ng * 128 + row] = acc0[mt];
            red[ng * 128 + row + 8] = acc1[mt];
        }
    }
    __syncthreads();
    if (tid < 128) {
        float p = red[tid] + red[128 + tid] + red[256 + tid] + red[384 + tid];
        g_partial[(blockIdx.z * NTN + blockIdx.x) * BDIM + m0 + tid] = p;
    }

    // ---- Last-CTA final reduction ----
    __shared__ unsigned s_old;
    __syncthreads();
    if (tid == 0) {
        __threadfence();
        s_old = atomicAdd(&g_cnt, 1u);
    }
    __syncthreads();
    if (s_old == NCTA - 1) {
        __threadfence();
        for (int m = tid; m < BDIM; m += 256) {
            float s = 0.0f;
#pragma unroll
            for (int p = 0; p < 2 * NTN; ++p) s += g_partial[p * BDIM + m];
            out[m] = s;
        }
        if (tid == 0) g_cnt = 0;  // reset for next graph replay
    }
}

// ---------------------------------------------------------------------------
extern "C" void kernel_launch(void* const* d_in, const int* in_sizes, int n_in,
                              void* d_out, int out_size) {
    const float* x = (const float*)d_in[0];  // [1024, 2048]
    const float* Q = (const float*)d_in[1];  // [2048, 2048]
    float* out = (float*)d_out;              // [1024]

    static bool attr_set = false;
    if (!attr_set) {
        cudaFuncSetAttribute(k_gemm, cudaFuncAttributeMaxDynamicSharedMemorySize,
                             SMEM_BYTES);
        attr_set = true;
    }

    k_prep<<<2048 + 1024, 256>>>(x, Q);
    k_gemm<<<dim3(NTN, MT, 2), 256, SMEM_BYTES>>>(x, out);
}

// round 9
// speedup vs baseline: 1.6147x; 1.1578x over previous
#include <cuda_runtime.h>
#include <cuda_bf16.h>
#include <cstdint>

// ============================================================================
// BinaryToCost: out[i] = x_i @ Q @ x_i  (x: 1024x2048 {0,1} fp32, Q: 2048^2 fp32)
// Key identity (x binary, x^2 = x):  x^T Q x = x^T U x with U upper-triangular,
//   U[j][n... stored as B[n][j] = (j<n ? Q_jn + Q_nj : (j==n ? Q_nn : 0)).
// => 44% fewer tensor MACs (triangular tile skipping), balanced via a flat
// 18-unit-per-CTA schedule with mid-CTA accumulator folds.
// Split-precision bf16 (U = Uhi + Ulo) against the measured sm_103 HMMA.f32
// per-SM rate ceiling; z-split over the two passes.
// ============================================================================

#define NDIM 2048
#define BDIM 1024
#define BM 128
#define BN 256
#define BK 64
#define NTN (NDIM / BN)     // 8 n-tiles
#define NUNITS 144          // sum of 4*(t+1), t=0..7
#define NSLICE 8
#define UPC (NUNITS / NSLICE)  // 18 units per CTA
#define MT (BDIM / BM)      // 8
#define NCTA (NSLICE * MT * 2) // 128
#define NSTAGE 4
#define A_BYTES 16384
#define B_BYTES 32768
#define STAGE_BYTES (A_BYTES + B_BYTES)
#define SMEM_BYTES (NSTAGE * STAGE_BYTES)  // 192 KB

// ---------------------------------------------------------------------------
__device__ __align__(16) __nv_bfloat16 g_xh[BDIM * NDIM];   // bf16(x) [m][k]
__device__ __align__(16) __nv_bfloat16 g_uhi[NDIM * NDIM];  // B[n][j] hi
__device__ __align__(16) __nv_bfloat16 g_ulo[NDIM * NDIM];  // B[n][j] lo
__device__ float g_partial[16 * BDIM];                      // [z*8+slice][m]
__device__ unsigned g_cnt = 0;

// ---------------------------------------------------------------------------
__device__ __forceinline__ uint32_t smem_u32(const void* p) {
    return (uint32_t)__cvta_generic_to_shared(p);
}
__device__ __forceinline__ uint32_t sw128(uint32_t off) {
    return off ^ ((off >> 3) & 0x70);
}
__device__ __forceinline__ void cp_async16(uint32_t dst, const void* src) {
    asm volatile("cp.async.cg.shared.global [%0], [%1], 16;"
                 :: "r"(dst), "l"(src) : "memory");
}

#define LDSM_X4(r, addr)                                                      \
    asm volatile("ldmatrix.sync.aligned.m8n8.x4.shared.b16 {%0,%1,%2,%3}, [%4];" \
                 : "=r"((r)[0]), "=r"((r)[1]), "=r"((r)[2]), "=r"((r)[3])     \
                 : "r"(addr))

__device__ __forceinline__ void mma16816(float* d, const uint32_t* a,
                                         const uint32_t* b) {
    asm volatile(
        "mma.sync.aligned.m16n8k16.row.col.f32.bf16.bf16.f32 "
        "{%0,%1,%2,%3}, {%4,%5,%6,%7}, {%8,%9}, {%0,%1,%2,%3};"
        : "+f"(d[0]), "+f"(d[1]), "+f"(d[2]), "+f"(d[3])
        : "r"(a[0]), "r"(a[1]), "r"(a[2]), "r"(a[3]), "r"(b[0]), "r"(b[1]));
}

// unit u (0..143) -> (t_n, chunk): t = largest t with 2t(t+1) <= u.
// 2u+1 = (2t+1)^2 at boundaries; exact in fp32 for u<=143.
__device__ __forceinline__ void unit_tc(int u, int& t, int& c) {
    t = (int)((__fsqrt_rn(2.0f * (float)u + 1.0f) - 1.0f) * 0.5f);
    c = u - 2 * t * (t + 1);
}

// ---------------------------------------------------------------------------
// Prep: blocks [0, 4096): build U 32x32 block (nb=b>>6, jb=b&63);
//       blocks [4096, 5120): pack x to bf16.
// ---------------------------------------------------------------------------
__global__ void __launch_bounds__(256)
k_prep(const float* __restrict__ x, const float* __restrict__ Q) {
    const int b = blockIdx.x;
    if (b < 4096) {
        const int nb = b >> 6, jb = b & 63;
        if (jb >= 8 * (nb / 8 + 1)) return;  // never read by any tile
        const int n0 = nb * 32, j0 = jb * 32;
        const int tx = threadIdx.x & 31, ty = threadIdx.x >> 5;  // 32 x 8

        if (jb > nb) {  // straddle-region zero block
            uint32_t zero4[4] = {0, 0, 0, 0};
#pragma unroll
            for (int r = 0; r < 4; ++r) {
                int a = ty + 8 * r;
                // 32 bf16 per row = 4 uint4 per row; thread tx covers 2 bf16
                __nv_bfloat162 z2; z2.x = __float2bfloat16(0.f); z2.y = z2.x;
                reinterpret_cast<__nv_bfloat162*>(
                    g_uhi + (n0 + a) * NDIM + j0)[tx & 15] = z2;
                reinterpret_cast<__nv_bfloat162*>(
                    g_ulo + (n0 + a) * NDIM + j0)[tx & 15] = z2;
            }
            (void)zero4;
            return;
        }

        __shared__ float S[32][33];
#pragma unroll
        for (int r = 0; r < 4; ++r)  // S[a][b] = Q[j0+a][n0+b]
            S[ty + 8 * r][tx] = Q[(j0 + ty + 8 * r) * NDIM + n0 + tx];
        __syncthreads();

#pragma unroll
        for (int r = 0; r < 4; ++r) {
            int a = ty + 8 * r;          // row in n
            int n = n0 + a, j = j0 + tx;
            float D = Q[n * NDIM + j];   // Q_nj
            float T = S[tx][a];          // Q_jn
            float u = (j < n) ? (D + T) : ((j == n) ? D : 0.0f);
            __nv_bfloat16 h = __float2bfloat16(u);
            g_uhi[n * NDIM + j] = h;
            g_ulo[n * NDIM + j] = __float2bfloat16(u - __bfloat162float(h));
        }
    } else {
        int i = (b - 4096) * 256 + threadIdx.x;  // 8-elem group over x
        const float4* x4 = reinterpret_cast<const float4*>(x) + i * 2;
        float4 v0 = x4[0], v1 = x4[1];
        __nv_bfloat162 p[4];
        p[0] = __floats2bfloat162_rn(v0.x, v0.y);
        p[1] = __floats2bfloat162_rn(v0.z, v0.w);
        p[2] = __floats2bfloat162_rn(v1.x, v1.y);
        p[3] = __floats2bfloat162_rn(v1.z, v1.w);
        reinterpret_cast<uint4*>(g_xh)[i] = *reinterpret_cast<uint4*>(p);
    }
}

// ---------------------------------------------------------------------------
// GEMM: grid (NSLICE, MT, 2). 256 threads, 8 warps (2M x 4N), warp 64x64.
// Each CTA runs 18 (t_n, chunk) units; folds accumulators at n-tile edges.
// ---------------------------------------------------------------------------
__global__ void __launch_bounds__(256, 1)
k_gemm(const float* __restrict__ x, float* __restrict__ out) {
    extern __shared__ __align__(1024) uint8_t smem[];

    const int tid = threadIdx.x;
    const int wid = tid >> 5;
    const int lane = tid & 31;
    const int slice = blockIdx.x;
    const int m0 = blockIdx.y * BM;
    const int wm = (wid >> 2) * 64;
    const int wn = (wid & 3) * 64;
    const int grp = lane >> 3;
    const int ri = lane & 7;
    const int g4 = lane >> 2;
    const int tc2 = (lane & 3) * 2;
    const __nv_bfloat16* __restrict__ us = blockIdx.z ? g_ulo : g_uhi;
    const int ubase = slice * UPC;

    auto stage_load = [&](int i) {
        int t, c;
        unit_tc(ubase + i, t, c);
        const int n0u = t * BN;
        const int kbE = c * BK;
        uint32_t sa = smem_u32(smem) + (i % NSTAGE) * STAGE_BYTES;
        uint32_t sb = sa + A_BYTES;
#pragma unroll
        for (int q = 0; q < 4; ++q) {  // A: 128 rows
            int g = tid + 256 * q;
            int rr = g >> 3, cc = g & 7;
            uint32_t off = sw128((uint32_t)(rr * 128 + cc * 16));
            cp_async16(sa + off, g_xh + (m0 + rr) * NDIM + kbE + cc * 8);
        }
#pragma unroll
        for (int q = 0; q < 8; ++q) {  // B: 256 rows
            int g = tid + 256 * q;
            int rr = g >> 3, cc = g & 7;
            uint32_t off = sw128((uint32_t)(rr * 128 + cc * 16));
            cp_async16(sb + off, us + (n0u + rr) * NDIM + kbE + cc * 8);
        }
        asm volatile("cp.async.commit_group;" ::: "memory");
    };

    float cfrag[4][8][4];
#pragma unroll
    for (int mt = 0; mt < 4; ++mt)
#pragma unroll
        for (int nt = 0; nt < 8; ++nt)
#pragma unroll
            for (int r = 0; r < 4; ++r) cfrag[mt][nt][r] = 0.0f;

    float facc0[4] = {0, 0, 0, 0}, facc1[4] = {0, 0, 0, 0};

    stage_load(0);
    stage_load(1);
    stage_load(2);

    for (int i = 0; i < UPC; ++i) {
        if (i < UPC - 2)
            asm volatile("cp.async.wait_group 2;" ::: "memory");
        else if (i == UPC - 2)
            asm volatile("cp.async.wait_group 1;" ::: "memory");
        else
            asm volatile("cp.async.wait_group 0;" ::: "memory");
        __syncthreads();

        if (i + 3 < UPC) stage_load(i + 3);

        const uint32_t sa = smem_u32(smem) + (i % NSTAGE) * STAGE_BYTES;
        const uint32_t sb = sa + A_BYTES;

#pragma unroll
        for (int s = 0; s < 4; ++s) {
            const int kb = s * 32;
            uint32_t a[4][4];
#pragma unroll
            for (int mt = 0; mt < 4; ++mt) {
                int row = wm + mt * 16 + (grp & 1) * 8 + ri;
                uint32_t addr = sa + sw128((uint32_t)(row * 128 + kb + (grp >> 1) * 16));
                LDSM_X4(a[mt], addr);
            }
            uint32_t b[4][4];
#pragma unroll
            for (int nt2 = 0; nt2 < 4; ++nt2) {
                int row = wn + nt2 * 16 + (grp >> 1) * 8 + ri;
                uint32_t addr = sb + sw128((uint32_t)(row * 128 + kb + (grp & 1) * 16));
                LDSM_X4(b[nt2], addr);
            }
#pragma unroll
            for (int mt = 0; mt < 4; ++mt)
#pragma unroll
                for (int nt = 0; nt < 8; ++nt)
                    mma16816(cfrag[mt][nt], a[mt], &b[nt >> 1][(nt & 1) * 2]);
        }

        // Fold at n-tile boundary or end of schedule: masked row-sum of cfrag
        // into persistent per-thread accumulators (linear & additive).
        int t, c;
        unit_tc(ubase + i, t, c);
        if (i == UPC - 1 || c == 4 * t + 3) {
            const int n0u = t * BN;
#pragma unroll
            for (int mt = 0; mt < 4; ++mt) {
                const int r0 = m0 + wm + mt * 16 + g4;
                float a0 = 0.0f, a1 = 0.0f;
#pragma unroll
                for (int nt = 0; nt < 8; ++nt) {
                    const int ng = n0u + wn + nt * 8 + tc2;
                    const float* x0 = x + r0 * NDIM + ng;
                    const float* x1 = x0 + 8 * NDIM;
                    a0 += cfrag[mt][nt][0] * x0[0] + cfrag[mt][nt][1] * x0[1];
                    a1 += cfrag[mt][nt][2] * x1[0] + cfrag[mt][nt][3] * x1[1];
#pragma unroll
                    for (int r = 0; r < 4; ++r) cfrag[mt][nt][r] = 0.0f;
                }
                facc0[mt] += a0;
                facc1[mt] += a1;
            }
        }
    }

    // ---- Final per-CTA reduce (deterministic) ----
#pragma unroll
    for (int mt = 0; mt < 4; ++mt) {
#pragma unroll
        for (int o = 1; o <= 2; o <<= 1) {
            facc0[mt] += __shfl_xor_sync(0xFFFFFFFF, facc0[mt], o);
            facc1[mt] += __shfl_xor_sync(0xFFFFFFFF, facc1[mt], o);
        }
    }
    __syncthreads();  // stage smem free
    float* red = reinterpret_cast<float*>(smem);  // [4 n-groups][128 rows]
    if ((lane & 3) == 0) {
        const int ng = wid & 3;
#pragma unroll
        for (int mt = 0; mt < 4; ++mt) {
            int row = wm + mt * 16 + g4;
            red[ng * 128 + row] = facc0[mt];
            red[ng * 128 + row + 8] = facc1[mt];
        }
    }
    __syncthreads();
    if (tid < 128) {
        float p = red[tid] + red[128 + tid] + red[256 + tid] + red[384 + tid];
        g_partial[(blockIdx.z * NSLICE + slice) * BDIM + m0 + tid] = p;
    }

    // ---- Last-CTA final reduction ----
    __shared__ unsigned s_old;
    __syncthreads();
    if (tid == 0) {
        __threadfence();
        s_old = atomicAdd(&g_cnt, 1u);
    }
    __syncthreads();
    if (s_old == NCTA - 1) {
        __threadfence();
        for (int m = tid; m < BDIM; m += 256) {
            float s = 0.0f;
#pragma unroll
            for (int p = 0; p < 16; ++p) s += g_partial[p * BDIM + m];
            out[m] = s;
        }
        if (tid == 0) g_cnt = 0;  // reset for next graph replay
    }
}

// ---------------------------------------------------------------------------
extern "C" void kernel_launch(void* const* d_in, const int* in_sizes, int n_in,
                              void* d_out, int out_size) {
    const float* x = (const float*)d_in[0];  // [1024, 2048]
    const float* Q = (const float*)d_in[1];  // [2048, 2048]
    float* out = (float*)d_out;              // [1024]

    static bool attr_set = false;
    if (!attr_set) {
        cudaFuncSetAttribute(k_gemm, cudaFuncAttributeMaxDynamicSharedMemorySize,
                             SMEM_BYTES);
        attr_set = true;
    }

    k_prep<<<4096 + 1024, 256>>>(x, Q);
    k_gemm<<<dim3(NSLICE, MT, 2), 256, SMEM_BYTES>>>(x, out);
}

// round 10
// speedup vs baseline: 1.9934x; 1.2346x over previous
#include <cuda_runtime.h>
#include <cuda_bf16.h>
#include <cstdint>

// ============================================================================
// BinaryToCost: out[i] = x_i @ Q @ x_i  (x: 1024x2048 {0,1} fp32, Q: 2048^2 fp32)
// x binary (x^2=x)  =>  x^T Q x = x^T U x, U upper-triangular folded:
//   B[n][j] = (j<n ? Q_jn + Q_nj : (j==n ? Q_nn : 0))  -> 44% fewer MACs.
// Split-precision bf16 (U = Uhi + Ulo), z-split over 2 passes, flat 18-unit
// per-CTA schedule, folds masked by a BIT-PACKED x table (cheap epilogue).
// ============================================================================

#define NDIM 2048
#define BDIM 1024
#define BM 128
#define BN 256
#define BK 64
#define NUNITS 144             // sum of 4*(t+1), t=0..7
#define NSLICE 8
#define UPC (NUNITS / NSLICE)  // 18 units per CTA
#define MT (BDIM / BM)         // 8
#define NCTA (NSLICE * MT * 2) // 128
#define NSTAGE 4
#define A_BYTES 16384
#define B_BYTES 32768
#define STAGE_BYTES (A_BYTES + B_BYTES)
#define SMEM_BYTES (NSTAGE * STAGE_BYTES)  // 192 KB

// ---------------------------------------------------------------------------
__device__ __align__(16) __nv_bfloat16 g_xh[BDIM * NDIM];   // bf16(x) [m][k]
__device__ __align__(16) __nv_bfloat16 g_uhi[NDIM * NDIM];  // B[n][j] hi
__device__ __align__(16) __nv_bfloat16 g_ulo[NDIM * NDIM];  // B[n][j] lo
__device__ __align__(16) unsigned long long g_xbits[BDIM * 32]; // [m][n/64]
__device__ float g_partial[16 * BDIM];                      // [z*8+slice][m]
__device__ unsigned g_cnt = 0;

// ---------------------------------------------------------------------------
__device__ __forceinline__ uint32_t smem_u32(const void* p) {
    return (uint32_t)__cvta_generic_to_shared(p);
}
__device__ __forceinline__ uint32_t sw128(uint32_t off) {
    return off ^ ((off >> 3) & 0x70);
}
__device__ __forceinline__ void cp_async16(uint32_t dst, const void* src) {
    asm volatile("cp.async.cg.shared.global [%0], [%1], 16;"
                 :: "r"(dst), "l"(src) : "memory");
}

#define LDSM_X4(r, addr)                                                      \
    asm volatile("ldmatrix.sync.aligned.m8n8.x4.shared.b16 {%0,%1,%2,%3}, [%4];" \
                 : "=r"((r)[0]), "=r"((r)[1]), "=r"((r)[2]), "=r"((r)[3])     \
                 : "r"(addr))

__device__ __forceinline__ void mma16816(float* d, const uint32_t* a,
                                         const uint32_t* b) {
    asm volatile(
        "mma.sync.aligned.m16n8k16.row.col.f32.bf16.bf16.f32 "
        "{%0,%1,%2,%3}, {%4,%5,%6,%7}, {%8,%9}, {%0,%1,%2,%3};"
        : "+f"(d[0]), "+f"(d[1]), "+f"(d[2]), "+f"(d[3])
        : "r"(a[0]), "r"(a[1]), "r"(a[2]), "r"(a[3]), "r"(b[0]), "r"(b[1]));
}

// unit u (0..143) -> (t_n, chunk): t = largest t with 2t(t+1) <= u.
__device__ __forceinline__ void unit_tc(int u, int& t, int& c) {
    t = (int)((__fsqrt_rn(2.0f * (float)u + 1.0f) - 1.0f) * 0.5f);
    c = u - 2 * t * (t + 1);
}

// ---------------------------------------------------------------------------
// Prep: b<4096: build U 32x32 block; b<5120: pack x bf16; else bitpack x.
// ---------------------------------------------------------------------------
__global__ void __launch_bounds__(256)
k_prep(const float* __restrict__ x, const float* __restrict__ Q) {
    const int b = blockIdx.x;
    if (b < 4096) {
        const int nb = b >> 6, jb = b & 63;
        if (jb >= 8 * (nb / 8 + 1)) return;  // never read by any tile
        const int n0 = nb * 32, j0 = jb * 32;
        const int tx = threadIdx.x & 31, ty = threadIdx.x >> 5;  // 32 x 8

        if (jb > nb) {  // straddle-region zero block
#pragma unroll
            for (int r = 0; r < 4; ++r) {
                int a = ty + 8 * r;
                __nv_bfloat162 z2; z2.x = __float2bfloat16(0.f); z2.y = z2.x;
                reinterpret_cast<__nv_bfloat162*>(
                    g_uhi + (n0 + a) * NDIM + j0)[tx & 15] = z2;
                reinterpret_cast<__nv_bfloat162*>(
                    g_ulo + (n0 + a) * NDIM + j0)[tx & 15] = z2;
            }
            return;
        }

        __shared__ float S[32][33];
#pragma unroll
        for (int r = 0; r < 4; ++r)  // S[a][b] = Q[j0+a][n0+b]
            S[ty + 8 * r][tx] = Q[(j0 + ty + 8 * r) * NDIM + n0 + tx];
        __syncthreads();

#pragma unroll
        for (int r = 0; r < 4; ++r) {
            int a = ty + 8 * r;
            int n = n0 + a, j = j0 + tx;
            float D = Q[n * NDIM + j];   // Q_nj
            float T = S[tx][a];          // Q_jn
            float u = (j < n) ? (D + T) : ((j == n) ? D : 0.0f);
            __nv_bfloat16 h = __float2bfloat16(u);
            g_uhi[n * NDIM + j] = h;
            g_ulo[n * NDIM + j] = __float2bfloat16(u - __bfloat162float(h));
        }
    } else if (b < 5120) {
        int i = (b - 4096) * 256 + threadIdx.x;  // 8-elem group over x
        const float4* x4 = reinterpret_cast<const float4*>(x) + i * 2;
        float4 v0 = x4[0], v1 = x4[1];
        __nv_bfloat162 p[4];
        p[0] = __floats2bfloat162_rn(v0.x, v0.y);
        p[1] = __floats2bfloat162_rn(v0.z, v0.w);
        p[2] = __floats2bfloat162_rn(v1.x, v1.y);
        p[3] = __floats2bfloat162_rn(v1.z, v1.w);
        reinterpret_cast<uint4*>(g_xh)[i] = *reinterpret_cast<uint4*>(p);
    } else {
        // bitpack x: g_xbits[m*32 + w], bit j = (x[m][64w+j] != 0)
        int b2 = b - 5120;                      // 256 blocks
        int wid = threadIdx.x >> 5;
        int lane = threadIdx.x & 31;
        int wbase = b2 * 128 + wid * 16;        // 32768 words total
#pragma unroll
        for (int j = 0; j < 16; ++j) {
            int widx = wbase + j;
            int m = widx >> 5, w = widx & 31;
            float v0 = x[m * NDIM + w * 64 + lane];
            float v1 = x[m * NDIM + w * 64 + 32 + lane];
            unsigned lo = __ballot_sync(0xFFFFFFFFu, v0 != 0.0f);
            unsigned hi = __ballot_sync(0xFFFFFFFFu, v1 != 0.0f);
            if (lane == 0)
                g_xbits[widx] = (unsigned long long)lo |
                                ((unsigned long long)hi << 32);
        }
    }
}

// ---------------------------------------------------------------------------
// GEMM: grid (NSLICE, MT, 2). 256 threads, 8 warps (2M x 4N), warp 64x64.
// Each CTA runs 18 (t_n, chunk) units; folds (bitmask-masked row sums) at
// n-tile boundaries into persistent per-thread accumulators.
// ---------------------------------------------------------------------------
__global__ void __launch_bounds__(256, 1)
k_gemm(float* __restrict__ out) {
    extern __shared__ __align__(1024) uint8_t smem[];

    const int tid = threadIdx.x;
    const int wid = tid >> 5;
    const int lane = tid & 31;
    const int slice = blockIdx.x;
    const int m0 = blockIdx.y * BM;
    const int wm = (wid >> 2) * 64;
    const int wn = (wid & 3) * 64;
    const int grp = lane >> 3;
    const int ri = lane & 7;
    const int g4 = lane >> 2;
    const int tc2 = (lane & 3) * 2;
    const __nv_bfloat16* __restrict__ us = blockIdx.z ? g_ulo : g_uhi;
    const int ubase = slice * UPC;

    auto stage_load = [&](int i) {
        int t, c;
        unit_tc(ubase + i, t, c);
        const int n0u = t * BN;
        const int kbE = c * BK;
        uint32_t sa = smem_u32(smem) + (i % NSTAGE) * STAGE_BYTES;
        uint32_t sb = sa + A_BYTES;
#pragma unroll
        for (int q = 0; q < 4; ++q) {  // A: 128 rows
            int g = tid + 256 * q;
            int rr = g >> 3, cc = g & 7;
            uint32_t off = sw128((uint32_t)(rr * 128 + cc * 16));
            cp_async16(sa + off, g_xh + (m0 + rr) * NDIM + kbE + cc * 8);
        }
#pragma unroll
        for (int q = 0; q < 8; ++q) {  // B: 256 rows
            int g = tid + 256 * q;
            int rr = g >> 3, cc = g & 7;
            uint32_t off = sw128((uint32_t)(rr * 128 + cc * 16));
            cp_async16(sb + off, us + (n0u + rr) * NDIM + kbE + cc * 8);
        }
        asm volatile("cp.async.commit_group;" ::: "memory");
    };

    float cfrag[4][8][4];
#pragma unroll
    for (int mt = 0; mt < 4; ++mt)
#pragma unroll
        for (int nt = 0; nt < 8; ++nt)
#pragma unroll
            for (int r = 0; r < 4; ++r) cfrag[mt][nt][r] = 0.0f;

    float facc0[4] = {0, 0, 0, 0}, facc1[4] = {0, 0, 0, 0};

    stage_load(0);
    stage_load(1);
    stage_load(2);

    for (int i = 0; i < UPC; ++i) {
        if (i < UPC - 2)
            asm volatile("cp.async.wait_group 2;" ::: "memory");
        else if (i == UPC - 2)
            asm volatile("cp.async.wait_group 1;" ::: "memory");
        else
            asm volatile("cp.async.wait_group 0;" ::: "memory");
        __syncthreads();

        if (i + 3 < UPC) stage_load(i + 3);

        const uint32_t sa = smem_u32(smem) + (i % NSTAGE) * STAGE_BYTES;
        const uint32_t sb = sa + A_BYTES;

#pragma unroll
        for (int s = 0; s < 4; ++s) {
            const int kb = s * 32;
            uint32_t a[4][4];
#pragma unroll
            for (int mt = 0; mt < 4; ++mt) {
                int row = wm + mt * 16 + (grp & 1) * 8 + ri;
                uint32_t addr = sa + sw128((uint32_t)(row * 128 + kb + (grp >> 1) * 16));
                LDSM_X4(a[mt], addr);
            }
            uint32_t b[4][4];
#pragma unroll
            for (int nt2 = 0; nt2 < 4; ++nt2) {
                int row = wn + nt2 * 16 + (grp >> 1) * 8 + ri;
                uint32_t addr = sb + sw128((uint32_t)(row * 128 + kb + (grp & 1) * 16));
                LDSM_X4(b[nt2], addr);
            }
#pragma unroll
            for (int mt = 0; mt < 4; ++mt)
#pragma unroll
                for (int nt = 0; nt < 8; ++nt)
                    mma16816(cfrag[mt][nt], a[mt], &b[nt >> 1][(nt & 1) * 2]);
        }

        // Fold at n-tile boundary / schedule end: bitmask-masked row sums.
        int t, c;
        unit_tc(ubase + i, t, c);
        if (i == UPC - 1 || c == 4 * t + 3) {
            const int nw = (t * BN + wn) >> 6;  // uint64 word per warp n-band
#pragma unroll
            for (int mt = 0; mt < 4; ++mt) {
                const int r0 = m0 + wm + mt * 16 + g4;
                const unsigned long long w0 = g_xbits[r0 * 32 + nw];
                const unsigned long long w1 = g_xbits[(r0 + 8) * 32 + nw];
                float a0 = 0.0f, a1 = 0.0f;
#pragma unroll
                for (int nt = 0; nt < 8; ++nt) {
                    const int bp = nt * 8 + tc2;
                    if ((w0 >> bp) & 1)       a0 += cfrag[mt][nt][0];
                    if ((w0 >> (bp + 1)) & 1) a0 += cfrag[mt][nt][1];
                    if ((w1 >> bp) & 1)       a1 += cfrag[mt][nt][2];
                    if ((w1 >> (bp + 1)) & 1) a1 += cfrag[mt][nt][3];
#pragma unroll
                    for (int r = 0; r < 4; ++r) cfrag[mt][nt][r] = 0.0f;
                }
                facc0[mt] += a0;
                facc1[mt] += a1;
            }
        }
    }

    // ---- Final per-CTA reduce (deterministic) ----
#pragma unroll
    for (int mt = 0; mt < 4; ++mt) {
#pragma unroll
        for (int o = 1; o <= 2; o <<= 1) {
            facc0[mt] += __shfl_xor_sync(0xFFFFFFFF, facc0[mt], o);
            facc1[mt] += __shfl_xor_sync(0xFFFFFFFF, facc1[mt], o);
        }
    }
    __syncthreads();  // stage smem free
    float* red = reinterpret_cast<float*>(smem);  // [4 n-groups][128 rows]
    if ((lane & 3) == 0) {
        const int ng = wid & 3;
#pragma unroll
        for (int mt = 0; mt < 4; ++mt) {
            int row = wm + mt * 16 + g4;
            red[ng * 128 + row] = facc0[mt];
            red[ng * 128 + row + 8] = facc1[mt];
        }
    }
    __syncthreads();
    if (tid < 128) {
        float p = red[tid] + red[128 + tid] + red[256 + tid] + red[384 + tid];
        g_partial[(blockIdx.z * NSLICE + slice) * BDIM + m0 + tid] = p;
    }

    // ---- Last-CTA final reduction ----
    __shared__ unsigned s_old;
    __syncthreads();
    if (tid == 0) {
        __threadfence();
        s_old = atomicAdd(&g_cnt, 1u);
    }
    __syncthreads();
    if (s_old == NCTA - 1) {
        __threadfence();
        for (int m = tid; m < BDIM; m += 256) {
            float s = 0.0f;
#pragma unroll
            for (int p = 0; p < 16; ++p) s += g_partial[p * BDIM + m];
            out[m] = s;
        }
        if (tid == 0) g_cnt = 0;  // reset for next graph replay
    }
}

// ---------------------------------------------------------------------------
extern "C" void kernel_launch(void* const* d_in, const int* in_sizes, int n_in,
                              void* d_out, int out_size) {
    const float* x = (const float*)d_in[0];  // [1024, 2048]
    const float* Q = (const float*)d_in[1];  // [2048, 2048]
    float* out = (float*)d_out;              // [1024]

    static bool attr_set = false;
    if (!attr_set) {
        cudaFuncSetAttribute(k_gemm, cudaFuncAttributeMaxDynamicSharedMemorySize,
                             SMEM_BYTES);
        attr_set = true;
    }

    k_prep<<<4096 + 1024 + 256, 256>>>(x, Q);
    k_gemm<<<dim3(NSLICE, MT, 2), 256, SMEM_BYTES>>>(out);
}